// round 9
// baseline (speedup 1.0000x reference)
#include <cuda_runtime.h>

// Problem dims (fixed by the reference setup_inputs)
#define B_    256
#define F_    300
#define JC_   1600
#define NC_   60
#define J4_   (JC_ / 4)    // 400 float4 per frame
#define CHUNK 30           // frames per pooling block
#define NCH   (F_ / CHUNK) // 10 chunks
#define NQ    (NC_ / 4)    // 15 n-quads
#define BTILE 16           // batch rows per fc block
#define BT_N  (B_ / BTILE) // 16 batch tiles

// Pooled (un-normalized) feature sums [B, JC] — 1.6 MB, built via red.global
__device__ float g_pooled[(size_t)B_ * JC_];

// ---------------------------------------------------------------------------
// Kernel 1: partial frame sums -> atomic accumulate into g_pooled.
// grid = (B, NCH), block = 400. (proven: ~36 us, near HBM floor)
// ---------------------------------------------------------------------------
__global__ __launch_bounds__(J4_) void pool_part_kernel(
    const float* __restrict__ x,       // [B, F, JC]
    const int*   __restrict__ lengths) // [B]
{
    const int b  = blockIdx.x;
    const int c  = blockIdx.y;
    const int j4 = threadIdx.x;

    const int len = lengths[b];
    const int f0  = c * CHUNK;
    if (f0 >= len) return;
    const int f1  = min(f0 + CHUNK, len);

    const float4* __restrict__ xb =
        reinterpret_cast<const float4*>(x + (size_t)b * F_ * JC_);

    float ax = 0.f, ay = 0.f, az = 0.f, aw = 0.f;
    int f = f0;
    for (; f + 4 <= f1; f += 4) {
        float4 v0 = __ldcs(&xb[(size_t)(f + 0) * J4_ + j4]);
        float4 v1 = __ldcs(&xb[(size_t)(f + 1) * J4_ + j4]);
        float4 v2 = __ldcs(&xb[(size_t)(f + 2) * J4_ + j4]);
        float4 v3 = __ldcs(&xb[(size_t)(f + 3) * J4_ + j4]);
        ax += v0.x + v1.x + v2.x + v3.x;
        ay += v0.y + v1.y + v2.y + v3.y;
        az += v0.z + v1.z + v2.z + v3.z;
        aw += v0.w + v1.w + v2.w + v3.w;
    }
    for (; f < f1; f++) {
        float4 v = __ldcs(&xb[(size_t)f * J4_ + j4]);
        ax += v.x; ay += v.y; az += v.z; aw += v.w;
    }

    float* dst = g_pooled + (size_t)b * JC_ + j4 * 4;
    asm volatile("red.global.add.v4.f32 [%0], {%1, %2, %3, %4};"
                 :: "l"(dst), "f"(ax), "f"(ay), "f"(az), "f"(aw)
                 : "memory");
}

// ---------------------------------------------------------------------------
// Kernel 2: FC with W-slice in SHARED memory (quad-major decomposition).
// grid = (NQ=15, BT_N=16) = 240 blocks, block = 256 (8 warps).
//  - Block (q, bt): load W[:, 4q..4q+3] into smem (25.6 KB, one gather pass).
//  - Warp w handles rows b = bt*16 + w and + w+8.
//    Lane l sweeps j = 32k + l: coalesced L2 load of the un-normalized
//    pooled row (or x frame 0 when len<=1) x conflict-free LDS.128 of sW.
//    8 independent FMA chains/warp; mean folded into the epilogue:
//    out = (sum_j xsum[j]*W[j,n]) * inv + bias[n].
// ---------------------------------------------------------------------------
__global__ __launch_bounds__(256) void fc_kernel(
    const float* __restrict__ x,       // [B, F, JC] (len<=1 edge case)
    const int*   __restrict__ lengths, // [B]
    const float* __restrict__ W,       // [JC, NC] row-major
    const float* __restrict__ bias,    // [NC]
    float*       __restrict__ out)     // [B, NC]
{
    __shared__ float4 sW[JC_];         // 25.6 KB: W[:, 4q..4q+3]

    const int q  = blockIdx.x;         // 0..14
    const int b0 = blockIdx.y * BTILE; // batch tile base
    const int t  = threadIdx.x;
    const int w  = t >> 5;             // 0..7
    const int l  = t & 31;

    // ---- load W slice into shared (1600 independent 16B gathers) ----
    const float4* __restrict__ W4 = reinterpret_cast<const float4*>(W); // [JC][15]
    for (int j = t; j < JC_; j += 256)
        sW[j] = W4[(size_t)j * NQ + q];
    __syncthreads();

    // ---- two rows per warp, fused in one sweep (8 FMA chains) ----
    const int bA = b0 + w;
    const int bB = b0 + w + 8;
    const int lenA = lengths[bA];
    const int lenB = lengths[bB];
    const float* __restrict__ srcA =
        (lenA <= 1) ? (x + (size_t)bA * F_ * JC_) : (g_pooled + (size_t)bA * JC_);
    const float* __restrict__ srcB =
        (lenB <= 1) ? (x + (size_t)bB * F_ * JC_) : (g_pooled + (size_t)bB * JC_);
    const float invA = (lenA <= 1) ? 1.0f : 1.0f / (float)lenA;
    const float invB = (lenB <= 1) ? 1.0f : 1.0f / (float)lenB;

    float4 a0 = make_float4(0.f, 0.f, 0.f, 0.f);
    float4 a1 = a0;

#pragma unroll 5
    for (int k = 0; k < JC_ / 32; k++) {   // 50 iterations
        const int j = k * 32 + l;
        const float pA = srcA[j];          // coalesced 128B warp load (L2)
        const float pB = srcB[j];
        const float4 wv = sW[j];           // conflict-free LDS.128
        a0.x += pA * wv.x; a0.y += pA * wv.y; a0.z += pA * wv.z; a0.w += pA * wv.w;
        a1.x += pB * wv.x; a1.y += pB * wv.y; a1.z += pB * wv.z; a1.w += pB * wv.w;
    }

    // warp-shuffle reduce all 8 components
#pragma unroll
    for (int off = 16; off > 0; off >>= 1) {
        a0.x += __shfl_xor_sync(0xFFFFFFFF, a0.x, off);
        a0.y += __shfl_xor_sync(0xFFFFFFFF, a0.y, off);
        a0.z += __shfl_xor_sync(0xFFFFFFFF, a0.z, off);
        a0.w += __shfl_xor_sync(0xFFFFFFFF, a0.w, off);
        a1.x += __shfl_xor_sync(0xFFFFFFFF, a1.x, off);
        a1.y += __shfl_xor_sync(0xFFFFFFFF, a1.y, off);
        a1.z += __shfl_xor_sync(0xFFFFFFFF, a1.z, off);
        a1.w += __shfl_xor_sync(0xFFFFFFFF, a1.w, off);
    }

    if (l == 0) {
        const int n = 4 * q;
        const float b0v = bias[n + 0], b1v = bias[n + 1];
        const float b2v = bias[n + 2], b3v = bias[n + 3];
        float* oA = out + (size_t)bA * NC_ + n;
        oA[0] = a0.x * invA + b0v; oA[1] = a0.y * invA + b1v;
        oA[2] = a0.z * invA + b2v; oA[3] = a0.w * invA + b3v;
        float* oB = out + (size_t)bB * NC_ + n;
        oB[0] = a1.x * invB + b0v; oB[1] = a1.y * invB + b1v;
        oB[2] = a1.z * invB + b2v; oB[3] = a1.w * invB + b3v;
    }
}

extern "C" void kernel_launch(void* const* d_in, const int* in_sizes, int n_in,
                              void* d_out, int out_size)
{
    const float* x       = (const float*)d_in[0];
    const int*   lengths = (const int*)  d_in[1];
    const float* W       = (const float*)d_in[2];
    const float* bias    = (const float*)d_in[3];
    float*       out     = (float*)d_out;

    // zero the accumulator (graph-capturable memset node; no allocation)
    void* pooled_ptr = nullptr;
    cudaGetSymbolAddress(&pooled_ptr, g_pooled);
    cudaMemsetAsync(pooled_ptr, 0, sizeof(float) * (size_t)B_ * JC_);

    dim3 grid_pool(B_, NCH);
    pool_part_kernel<<<grid_pool, J4_>>>(x, lengths);
    dim3 grid_fc(NQ, BT_N);
    fc_kernel<<<grid_fc, 256>>>(x, lengths, W, bias, out);
}